// round 11
// baseline (speedup 1.0000x reference)
#include <cuda_runtime.h>
#include <cuda_bf16.h>
#include <cstdint>

// ---------------- problem constants ----------------
#define L_SEQ   4096      // F*P = 16*256
#define DM      1024
#define DI      2048
#define DSTATE  16
#define DTRANK  64
#define XDBL_W  96        // DTRANK + 2*DSTATE
#define HID     4096
#define NCHUNK  16
#define CHUNKL  256       // L_SEQ / NCHUNK
#define POOLED  256       // 16 * 4 * 4

// smem geometry (bf16 units) for pure-bf16 GEMM, 2 stages
#define APL     (128 * 40)             // A plane: 128 rows x (32+8) bf16
#define BPL     (32 * 136)             // B plane: 32 rows x (128+8) bf16
#define STG_BF  (2 * APL + 2 * BPL)    // 18944 bf16 = 37888 B per stage
#define SMEM_DYN_BYTES (2 * STG_BF * 2)  // 75776 B

typedef __nv_bfloat16 bf16;

// ---------------- scratch (device globals; no cudaMalloc allowed) ----------------
__device__ float g_xz   [L_SEQ * 2 * DI];
__device__ float g_u    [L_SEQ * DI];
__device__ float g_xdbl [L_SEQ * XDBL_W];
__device__ float g_dt   [L_SEQ * DI];
__device__ float g_mamba[L_SEQ * DM];
__device__ float g_ln2  [L_SEQ * DM];
__device__ float g_A2   [DI * DSTATE];
__device__ float g_Ap   [NCHUNK * DI * DSTATE];
__device__ float g_Be   [NCHUNK * DI * DSTATE];
__device__ float g_hin  [NCHUNK * DI * DSTATE];
__device__ float g_part [8 * POOLED * HID];    // split-K partials

// activation bf16 hi/lo planes
__device__ __align__(16) bf16 g_lnH [L_SEQ * DM],  g_lnL [L_SEQ * DM];
__device__ __align__(16) bf16 g_uH  [L_SEQ * DI],  g_uL  [L_SEQ * DI];
__device__ __align__(16) bf16 g_xdH [L_SEQ * XDBL_W], g_xdL[L_SEQ * XDBL_W];
__device__ __align__(16) bf16 g_yH  [L_SEQ * DI],  g_yL  [L_SEQ * DI];
__device__ __align__(16) bf16 g_poolH[POOLED * DM], g_poolL[POOLED * DM];
__device__ __align__(16) bf16 g_midH[POOLED * HID], g_midL[POOLED * HID];
// weight bf16 hi/lo planes ([K][N] layout, same as fp32 source)
__device__ __align__(16) bf16 g_wiH [DM * 2 * DI],  g_wiL [DM * 2 * DI];
__device__ __align__(16) bf16 g_wxH [DI * XDBL_W],  g_wxL [DI * XDBL_W];
__device__ __align__(16) bf16 g_wdH [DTRANK * DI],  g_wdL [DTRANK * DI];
__device__ __align__(16) bf16 g_woH [DI * DM],      g_woL [DI * DM];
__device__ __align__(16) bf16 g_w1H [DM * HID],     g_w1L [DM * HID];
__device__ __align__(16) bf16 g_w2H [HID * HID],    g_w2L [HID * HID];

// ---------------- helpers ----------------
__device__ __forceinline__ float siluf(float x) { return x / (1.f + __expf(-x)); }
__device__ __forceinline__ float softplusf(float x) { return (x > 20.f) ? x : log1pf(__expf(x)); }
__device__ __forceinline__ float gelu_exact(float x) {
    return 0.5f * x * (1.f + erff(x * 0.70710678118654752440f));
}

__device__ __forceinline__ uint32_t pack_bf(float a, float b) {   // low = a, high = b
    uint32_t r;
    asm("cvt.rn.bf16x2.f32 %0, %1, %2;" : "=r"(r) : "f"(b), "f"(a));
    return r;
}
__device__ __forceinline__ void split1(float v, bf16& h, bf16& l) {
    h = __float2bfloat16_rn(v);
    l = __float2bfloat16_rn(v - __bfloat162float(h));
}

__device__ __forceinline__ void cp_async16(const void* dst_smem, const void* src_gmem, bool pred) {
    uint32_t d = (uint32_t)__cvta_generic_to_shared(dst_smem);
    int sz = pred ? 16 : 0;
    asm volatile("cp.async.cg.shared.global [%0], [%1], 16, %2;\n"
                 :: "r"(d), "l"(src_gmem), "r"(sz));
}
__device__ __forceinline__ void cp_commit() { asm volatile("cp.async.commit_group;\n"); }
template<int N>
__device__ __forceinline__ void cp_wait() { asm volatile("cp.async.wait_group %0;\n" :: "n"(N)); }

__device__ __forceinline__ void ldsm_x2_t(uint32_t& r0, uint32_t& r1, const void* p) {
    uint32_t a = (uint32_t)__cvta_generic_to_shared(p);
    asm volatile("ldmatrix.sync.aligned.m8n8.x2.trans.shared.b16 {%0,%1}, [%2];"
                 : "=r"(r0), "=r"(r1) : "r"(a));
}

__device__ __forceinline__ void mma_bf16(float* c, const uint32_t* a, const uint32_t* b) {
    asm volatile(
        "mma.sync.aligned.m16n8k16.row.col.f32.bf16.bf16.f32 "
        "{%0,%1,%2,%3}, {%4,%5,%6,%7}, {%8,%9}, {%0,%1,%2,%3};\n"
        : "+f"(c[0]), "+f"(c[1]), "+f"(c[2]), "+f"(c[3])
        : "r"(a[0]), "r"(a[1]), "r"(a[2]), "r"(a[3]), "r"(b[0]), "r"(b[1]));
}

// ---------------- weight split: fp32 -> bf16 hi/lo planes ----------------
__global__ void wsplit_k(const float* __restrict__ W, bf16* __restrict__ H,
                         bf16* __restrict__ L, int n4) {
    int i = blockIdx.x * blockDim.x + threadIdx.x;
    if (i >= n4) return;
    float4 v = reinterpret_cast<const float4*>(W)[i];
    uint32_t h01 = pack_bf(v.x, v.y);
    uint32_t h23 = pack_bf(v.z, v.w);
    float hx = __uint_as_float(h01 << 16), hy = __uint_as_float(h01 & 0xFFFF0000u);
    float hz = __uint_as_float(h23 << 16), hw = __uint_as_float(h23 & 0xFFFF0000u);
    uint32_t l01 = pack_bf(v.x - hx, v.y - hy);
    uint32_t l23 = pack_bf(v.z - hz, v.w - hw);
    reinterpret_cast<uint2*>(H)[i] = make_uint2(h01, h23);
    reinterpret_cast<uint2*>(L)[i] = make_uint2(l01, l23);
}

// ---------------- layernorm (fp32 out) ----------------
__global__ void layernorm_k(const float* __restrict__ x, float* __restrict__ o,
                            const float* __restrict__ w, const float* __restrict__ b,
                            int cols) {
    int row = blockIdx.x;
    const float* xr = x + (size_t)row * cols;
    float s = 0.f, s2 = 0.f;
    for (int c = threadIdx.x; c < cols; c += blockDim.x) {
        float v = xr[c];
        s += v; s2 += v * v;
    }
    __shared__ float shs[8], shs2[8], shmu, shinv;
    for (int off = 16; off; off >>= 1) {
        s  += __shfl_down_sync(0xffffffffu, s,  off);
        s2 += __shfl_down_sync(0xffffffffu, s2, off);
    }
    int wid = threadIdx.x >> 5, lid = threadIdx.x & 31;
    if (!lid) { shs[wid] = s; shs2[wid] = s2; }
    __syncthreads();
    if (threadIdx.x == 0) {
        float ts = 0.f, ts2 = 0.f;
        int nw = blockDim.x >> 5;
        for (int i = 0; i < nw; ++i) { ts += shs[i]; ts2 += shs2[i]; }
        float mu = ts / cols;
        shmu = mu;
        shinv = rsqrtf(ts2 / cols - mu * mu + 1e-5f);
    }
    __syncthreads();
    float mu = shmu, inv = shinv;
    float* orow = o + (size_t)row * cols;
    for (int c = threadIdx.x; c < cols; c += blockDim.x)
        orow[c] = (xr[c] - mu) * inv * w[c] + b[c];
}

// ---------------- layernorm (bf16 hi/lo out) ----------------
__global__ void layernorm_bf_k(const float* __restrict__ x, bf16* __restrict__ oh,
                               bf16* __restrict__ ol, const float* __restrict__ w,
                               const float* __restrict__ b, int cols) {
    int row = blockIdx.x;
    const float* xr = x + (size_t)row * cols;
    float s = 0.f, s2 = 0.f;
    for (int c = threadIdx.x; c < cols; c += blockDim.x) {
        float v = xr[c];
        s += v; s2 += v * v;
    }
    __shared__ float shs[8], shs2[8], shmu, shinv;
    for (int off = 16; off; off >>= 1) {
        s  += __shfl_down_sync(0xffffffffu, s,  off);
        s2 += __shfl_down_sync(0xffffffffu, s2, off);
    }
    int wid = threadIdx.x >> 5, lid = threadIdx.x & 31;
    if (!lid) { shs[wid] = s; shs2[wid] = s2; }
    __syncthreads();
    if (threadIdx.x == 0) {
        float ts = 0.f, ts2 = 0.f;
        int nw = blockDim.x >> 5;
        for (int i = 0; i < nw; ++i) { ts += shs[i]; ts2 += shs2[i]; }
        float mu = ts / cols;
        shmu = mu;
        shinv = rsqrtf(ts2 / cols - mu * mu + 1e-5f);
    }
    __syncthreads();
    float mu = shmu, inv = shinv;
    for (int c = threadIdx.x; c < cols; c += blockDim.x) {
        float v = (xr[c] - mu) * inv * w[c] + b[c];
        bf16 h, l; split1(v, h, l);
        oh[(size_t)row * cols + c] = h;
        ol[(size_t)row * cols + c] = l;
    }
}

// ---------------- pure-bf16 tensor-core GEMM (pre-split hi/lo planes) ----------------
// C[M,N] = epi(A@B) with A planes [M][K] row-major, B planes [K][N] row-major.
// C = Ah*Bh + Ah*Bl + Al*Bh  (exactly the R8 arithmetic, conversions hoisted out).
// Block 128x128x32, 512 thr = 16 warps (4x4), warp tile 32x32, 2-stage cp.async.
// EPI: 0 none, 1 bias+softplus, 2 +residual, 3 bias+gelu, 4 bias
template<int EPI>
__device__ __forceinline__ float epi_apply(float v, int r, int c,
                                           const float* bias,
                                           const float* res, int ldres) {
    if (EPI == 1) return softplusf(v + bias[c]);
    if (EPI == 2) return v + res[(size_t)r * ldres + c];
    if (EPI == 3) return gelu_exact(v + bias[c]);
    if (EPI == 4) return v + bias[c];
    return v;
}

template<int EPI>
__global__ __launch_bounds__(512, 1)
void gemm_bfp_k(const bf16* __restrict__ Ah, const bf16* __restrict__ Al, int lda,
                const bf16* __restrict__ Bh, const bf16* __restrict__ Bl, int ldb,
                float* __restrict__ C, int ldc,
                float* __restrict__ Cpart,
                const float* __restrict__ bias,
                const float* __restrict__ res, int ldres,
                int M, int N, int K) {
    extern __shared__ bf16 smb[];
    const int tid  = threadIdx.x;
    const int warp = tid >> 5;
    const int lane = tid & 31;
    const int grp  = lane >> 2;     // 0..7
    const int tig  = lane & 3;      // 0..3
    const int wm   = warp >> 2;     // 0..3
    const int wn   = warp & 3;      // 0..3
    const int row0 = blockIdx.y * 128;
    const int col0 = blockIdx.x * 128;
    const int kLen = K / gridDim.z;
    const int kBeg = blockIdx.z * kLen;
    const int nK   = kLen / 32;

    // loader coords
    const int rA = tid >> 2, sA = tid & 3;    // A: 128 rows x 4 segs of 8 bf16
    const int rB = tid >> 4, sB = tid & 15;   // B: 32 rows x 16 segs of 8 bf16
    const bool bp = (col0 + sB * 8 + 8) <= N;

    float acc[2][4][4];
    #pragma unroll
    for (int i = 0; i < 2; ++i)
        #pragma unroll
        for (int j = 0; j < 4; ++j)
            #pragma unroll
            for (int q = 0; q < 4; ++q) acc[i][j][q] = 0.f;

    auto issue_tile = [&](int stage, int k0) {
        bf16* S = smb + stage * STG_BF;
        cp_async16(S + rA * 40 + sA * 8,
                   Ah + (size_t)(row0 + rA) * lda + k0 + sA * 8, true);
        cp_async16(S + APL + rA * 40 + sA * 8,
                   Al + (size_t)(row0 + rA) * lda + k0 + sA * 8, true);
        cp_async16(S + 2 * APL + rB * 136 + sB * 8,
                   Bh + (size_t)(k0 + rB) * ldb + col0 + sB * 8, bp);
        cp_async16(S + 2 * APL + BPL + rB * 136 + sB * 8,
                   Bl + (size_t)(k0 + rB) * ldb + col0 + sB * 8, bp);
        cp_commit();
    };

    issue_tile(0, kBeg);

    for (int kt = 0; kt < nK; ++kt) {
        if (kt + 1 < nK) {
            issue_tile((kt + 1) & 1, kBeg + (kt + 1) * 32);
            cp_wait<1>();
        } else {
            cp_wait<0>();
        }
        __syncthreads();

        const bf16* S   = smb + (kt & 1) * STG_BF;
        const bf16* sAh = S;
        const bf16* sAl = S + APL;
        const bf16* sBh = S + 2 * APL;
        const bf16* sBl = S + 2 * APL + BPL;
        const int lsel = lane & 15;

        #pragma unroll
        for (int ks = 0; ks < 32; ks += 16) {
            uint32_t afh[2][4], afl[2][4], bfh[4][2], bfl[4][2];
            #pragma unroll
            for (int i = 0; i < 2; ++i) {
                int mb = (wm * 32 + i * 16 + grp) * 40 + ks + 2 * tig;
                afh[i][0] = *reinterpret_cast<const uint32_t*>(sAh + mb);
                afh[i][1] = *reinterpret_cast<const uint32_t*>(sAh + mb + 8 * 40);
                afh[i][2] = *reinterpret_cast<const uint32_t*>(sAh + mb + 8);
                afh[i][3] = *reinterpret_cast<const uint32_t*>(sAh + mb + 8 * 40 + 8);
                afl[i][0] = *reinterpret_cast<const uint32_t*>(sAl + mb);
                afl[i][1] = *reinterpret_cast<const uint32_t*>(sAl + mb + 8 * 40);
                afl[i][2] = *reinterpret_cast<const uint32_t*>(sAl + mb + 8);
                afl[i][3] = *reinterpret_cast<const uint32_t*>(sAl + mb + 8 * 40 + 8);
            }
            #pragma unroll
            for (int j = 0; j < 4; ++j) {
                int n0 = wn * 32 + j * 8;
                ldsm_x2_t(bfh[j][0], bfh[j][1], sBh + (ks + lsel) * 136 + n0);
                ldsm_x2_t(bfl[j][0], bfl[j][1], sBl + (ks + lsel) * 136 + n0);
            }
            #pragma unroll
            for (int i = 0; i < 2; ++i)
                #pragma unroll
                for (int j = 0; j < 4; ++j) {
                    mma_bf16(acc[i][j], afh[i], bfh[j]);
                    mma_bf16(acc[i][j], afh[i], bfl[j]);
                    mma_bf16(acc[i][j], afl[i], bfh[j]);
                }
        }
        __syncthreads();
    }

    // -------- write out --------
    if (gridDim.z > 1) {
        float* P = Cpart + (size_t)blockIdx.z * M * N;
        #pragma unroll
        for (int i = 0; i < 2; ++i)
            #pragma unroll
            for (int j = 0; j < 4; ++j) {
                int r = row0 + wm * 32 + i * 16 + grp;
                int c = col0 + wn * 32 + j * 8 + tig * 2;
                if (c < N) {
                    P[(size_t)r * N + c]       = acc[i][j][0];
                    P[(size_t)(r + 8) * N + c] = acc[i][j][2];
                }
                if (c + 1 < N) {
                    P[(size_t)r * N + c + 1]       = acc[i][j][1];
                    P[(size_t)(r + 8) * N + c + 1] = acc[i][j][3];
                }
            }
    } else {
        #pragma unroll
        for (int i = 0; i < 2; ++i)
            #pragma unroll
            for (int j = 0; j < 4; ++j) {
                int r = row0 + wm * 32 + i * 16 + grp;
                int c = col0 + wn * 32 + j * 8 + tig * 2;
                if (c < N) {
                    C[(size_t)r * ldc + c]       = epi_apply<EPI>(acc[i][j][0], r,     c,     bias, res, ldres);
                    C[(size_t)(r + 8) * ldc + c] = epi_apply<EPI>(acc[i][j][2], r + 8, c,     bias, res, ldres);
                }
                if (c + 1 < N) {
                    C[(size_t)r * ldc + c + 1]       = epi_apply<EPI>(acc[i][j][1], r,     c + 1, bias, res, ldres);
                    C[(size_t)(r + 8) * ldc + c + 1] = epi_apply<EPI>(acc[i][j][3], r + 8, c + 1, bias, res, ldres);
                }
            }
    }
}

// ---------------- split-K reduction w/ epilogue; optional fp32 + bf16 hi/lo out ----------------
template<int EPI, int WF, int WB>
__global__ void reduceK_k(const float* __restrict__ part, int S, int MN, int N,
                          const float* __restrict__ bias,
                          float* __restrict__ outF,
                          bf16* __restrict__ outH, bf16* __restrict__ outL) {
    int idx4 = blockIdx.x * blockDim.x + threadIdx.x;
    if (idx4 * 4 >= MN) return;
    float4 s = make_float4(0.f, 0.f, 0.f, 0.f);
    for (int z = 0; z < S; ++z) {
        float4 v = *reinterpret_cast<const float4*>(part + (size_t)z * MN + idx4 * 4);
        s.x += v.x; s.y += v.y; s.z += v.z; s.w += v.w;
    }
    int c = (idx4 * 4) % N;
    if (EPI == 3) {
        s.x = gelu_exact(s.x + bias[c]);
        s.y = gelu_exact(s.y + bias[c + 1]);
        s.z = gelu_exact(s.z + bias[c + 2]);
        s.w = gelu_exact(s.w + bias[c + 3]);
    } else if (EPI == 4) {
        s.x += bias[c]; s.y += bias[c + 1]; s.z += bias[c + 2]; s.w += bias[c + 3];
    }
    if (WF) reinterpret_cast<float4*>(outF)[idx4] = s;
    if (WB) {
        uint32_t h01 = pack_bf(s.x, s.y), h23 = pack_bf(s.z, s.w);
        float hx = __uint_as_float(h01 << 16), hy = __uint_as_float(h01 & 0xFFFF0000u);
        float hz = __uint_as_float(h23 << 16), hw = __uint_as_float(h23 & 0xFFFF0000u);
        uint32_t l01 = pack_bf(s.x - hx, s.y - hy);
        uint32_t l23 = pack_bf(s.z - hz, s.w - hw);
        reinterpret_cast<uint2*>(outH)[idx4] = make_uint2(h01, h23);
        reinterpret_cast<uint2*>(outL)[idx4] = make_uint2(l01, l23);
    }
}

// ---------------- depthwise causal conv (k=4) + silu; fp32 + bf16 hi/lo out ----------------
__global__ void conv_silu_k(const float* __restrict__ xz, const float* __restrict__ w,
                            const float* __restrict__ b, float* __restrict__ u,
                            bf16* __restrict__ uH, bf16* __restrict__ uL) {
    int t = blockIdx.x * blockDim.x + threadIdx.x;
    if (t >= L_SEQ * DI) return;
    int l = t >> 11;
    int c = t & (DI - 1);
    float acc = b[c];
    #pragma unroll
    for (int k = 0; k < 4; ++k) {
        int ls = l - 3 + k;
        if (ls >= 0) acc = fmaf(w[c * 4 + k], xz[(size_t)ls * (2 * DI) + c], acc);
    }
    float v = siluf(acc);
    u[t] = v;
    bf16 h, lo; split1(v, h, lo);
    uH[t] = h; uL[t] = lo;
}

// ---------------- A2 = -exp(A_log) * log2(e) ----------------
__global__ void a2_k(const float* __restrict__ A_log, float* __restrict__ A2) {
    int t = blockIdx.x * blockDim.x + threadIdx.x;
    if (t < DI * DSTATE) A2[t] = -__expf(A_log[t]) * 1.44269504088896f;
}

// ---------------- scan pass 1: per-chunk summaries, thread per (chunk,d) ----------------
__global__ void scan1_k(const float* __restrict__ dt, const float* __restrict__ u,
                        const float* __restrict__ xdbl, const float* __restrict__ A2,
                        float* __restrict__ Ap, float* __restrict__ Be) {
    int t = blockIdx.x * blockDim.x + threadIdx.x;
    if (t >= NCHUNK * DI) return;
    int chunk = t >> 11;
    int d = t & (DI - 1);
    float h[DSTATE], ap[DSTATE], a2[DSTATE];
    #pragma unroll
    for (int n = 0; n < DSTATE; ++n) {
        h[n] = 0.f; ap[n] = 1.f; a2[n] = A2[d * DSTATE + n];
    }
    int l0 = chunk * CHUNKL;
    for (int s = 0; s < CHUNKL; ++s) {
        int l = l0 + s;
        float dtv = dt[(size_t)l * DI + d];
        float uv  = u [(size_t)l * DI + d];
        float du  = dtv * uv;
        #pragma unroll
        for (int n = 0; n < DSTATE; ++n) {
            float a = exp2f(dtv * a2[n]);
            ap[n] *= a;
            h[n] = fmaf(a, h[n], du * xdbl[l * XDBL_W + DTRANK + n]);
        }
    }
    #pragma unroll
    for (int n = 0; n < DSTATE; ++n) {
        int idx = (chunk << 15) | (n << 11) | d;
        Ap[idx] = ap[n];
        Be[idx] = h[n];
    }
}

// ---------------- scan pass 2: inter-chunk sequential scan ----------------
__global__ void scan2_k(const float* __restrict__ Ap, const float* __restrict__ Be,
                        float* __restrict__ hin) {
    int t = blockIdx.x * blockDim.x + threadIdx.x;
    if (t >= DI * DSTATE) return;
    float h = 0.f;
    #pragma unroll
    for (int c = 0; c < NCHUNK; ++c) {
        hin[c * (DI * DSTATE) + t] = h;
        h = fmaf(Ap[c * (DI * DSTATE) + t], h, Be[c * (DI * DSTATE) + t]);
    }
}

// ---------------- scan pass 3: recompute + y, D-skip, silu gate; bf16 hi/lo out ----------------
__global__ void scan3_k(const float* __restrict__ dt, const float* __restrict__ u,
                        const float* __restrict__ xdbl, const float* __restrict__ A2,
                        const float* __restrict__ hin, const float* __restrict__ Dp,
                        const float* __restrict__ xz,
                        bf16* __restrict__ yH, bf16* __restrict__ yL) {
    int t = blockIdx.x * blockDim.x + threadIdx.x;
    if (t >= NCHUNK * DI) return;
    int chunk = t >> 11;
    int d = t & (DI - 1);
    float h[DSTATE], a2[DSTATE];
    #pragma unroll
    for (int n = 0; n < DSTATE; ++n) {
        h[n]  = hin[chunk * (DI * DSTATE) + n * DI + d];
        a2[n] = A2[d * DSTATE + n];
    }
    float Dd = Dp[d];
    int l0 = chunk * CHUNKL;
    for (int s = 0; s < CHUNKL; ++s) {
        int l = l0 + s;
        float dtv = dt[(size_t)l * DI + d];
        float uv  = u [(size_t)l * DI + d];
        float du  = dtv * uv;
        float acc = 0.f;
        #pragma unroll
        for (int n = 0; n < DSTATE; ++n) {
            float a = exp2f(dtv * a2[n]);
            h[n] = fmaf(a, h[n], du * xdbl[l * XDBL_W + DTRANK + n]);
            acc  = fmaf(h[n], xdbl[l * XDBL_W + DTRANK + DSTATE + n], acc);
        }
        acc = fmaf(uv, Dd, acc);
        float zv = xz[(size_t)l * (2 * DI) + DI + d];
        float yv = acc * siluf(zv);
        bf16 hh, ll; split1(yv, hh, ll);
        yH[(size_t)l * DI + d] = hh;
        yL[(size_t)l * DI + d] = ll;
    }
}

// ---------------- avg pool 4x4 over (h,w); bf16 hi/lo out ----------------
__global__ void pool_k(const float* __restrict__ x, bf16* __restrict__ oh,
                       bf16* __restrict__ ol) {
    int t = blockIdx.x * blockDim.x + threadIdx.x;
    if (t >= POOLED * DM) return;
    int d = t & (DM - 1);
    int po = t >> 10;
    int f = po >> 4, hh = (po >> 2) & 3, ww = po & 3;
    float s = 0.f;
    #pragma unroll
    for (int i = 0; i < 4; ++i)
        #pragma unroll
        for (int j = 0; j < 4; ++j) {
            int l = f * 256 + (hh * 4 + i) * 16 + (ww * 4 + j);
            s += x[(size_t)l * DM + d];
        }
    s *= 0.0625f;
    bf16 h, l; split1(s, h, l);
    oh[t] = h; ol[t] = l;
}

// ---------------- launch ----------------
extern "C" void kernel_launch(void* const* d_in, const int* in_sizes, int n_in,
                              void* d_out, int out_size) {
    const float* vst        = (const float*)d_in[0];
    const float* ln_w       = (const float*)d_in[1];
    const float* ln_b       = (const float*)d_in[2];
    const float* in_proj_w  = (const float*)d_in[3];
    const float* conv_w     = (const float*)d_in[4];
    const float* conv_b     = (const float*)d_in[5];
    const float* x_proj_w   = (const float*)d_in[6];
    const float* dt_proj_w  = (const float*)d_in[7];
    const float* dt_proj_b  = (const float*)d_in[8];
    const float* A_log      = (const float*)d_in[9];
    const float* D_param    = (const float*)d_in[10];
    const float* out_proj_w = (const float*)d_in[11];
    const float* fln_w      = (const float*)d_in[12];
    const float* fln_b      = (const float*)d_in[13];
    const float* mlp_w1     = (const float*)d_in[14];
    const float* mlp_b1     = (const float*)d_in[15];
    const float* mlp_w2     = (const float*)d_in[16];
    const float* mlp_b2     = (const float*)d_in[17];
    float* out = (float*)d_out;

    float *p_xz, *p_u, *p_xdbl, *p_dt, *p_mamba, *p_ln2, *p_A2, *p_Ap, *p_Be, *p_hin, *p_part;
    bf16 *p_lnH, *p_lnL, *p_uH, *p_uL, *p_xdH, *p_xdL, *p_yH, *p_yL,
         *p_poolH, *p_poolL, *p_midH, *p_midL,
         *p_wiH, *p_wiL, *p_wxH, *p_wxL, *p_wdH, *p_wdL, *p_woH, *p_woL,
         *p_w1H, *p_w1L, *p_w2H, *p_w2L;
    cudaGetSymbolAddress((void**)&p_xz,    g_xz);
    cudaGetSymbolAddress((void**)&p_u,     g_u);
    cudaGetSymbolAddress((void**)&p_xdbl,  g_xdbl);
    cudaGetSymbolAddress((void**)&p_dt,    g_dt);
    cudaGetSymbolAddress((void**)&p_mamba, g_mamba);
    cudaGetSymbolAddress((void**)&p_ln2,   g_ln2);
    cudaGetSymbolAddress((void**)&p_A2,    g_A2);
    cudaGetSymbolAddress((void**)&p_Ap,    g_Ap);
    cudaGetSymbolAddress((void**)&p_Be,    g_Be);
    cudaGetSymbolAddress((void**)&p_hin,   g_hin);
    cudaGetSymbolAddress((void**)&p_part,  g_part);
    cudaGetSymbolAddress((void**)&p_lnH,   g_lnH);   cudaGetSymbolAddress((void**)&p_lnL, g_lnL);
    cudaGetSymbolAddress((void**)&p_uH,    g_uH);    cudaGetSymbolAddress((void**)&p_uL,  g_uL);
    cudaGetSymbolAddress((void**)&p_xdH,   g_xdH);   cudaGetSymbolAddress((void**)&p_xdL, g_xdL);
    cudaGetSymbolAddress((void**)&p_yH,    g_yH);    cudaGetSymbolAddress((void**)&p_yL,  g_yL);
    cudaGetSymbolAddress((void**)&p_poolH, g_poolH); cudaGetSymbolAddress((void**)&p_poolL, g_poolL);
    cudaGetSymbolAddress((void**)&p_midH,  g_midH);  cudaGetSymbolAddress((void**)&p_midL, g_midL);
    cudaGetSymbolAddress((void**)&p_wiH,   g_wiH);   cudaGetSymbolAddress((void**)&p_wiL, g_wiL);
    cudaGetSymbolAddress((void**)&p_wxH,   g_wxH);   cudaGetSymbolAddress((void**)&p_wxL, g_wxL);
    cudaGetSymbolAddress((void**)&p_wdH,   g_wdH);   cudaGetSymbolAddress((void**)&p_wdL, g_wdL);
    cudaGetSymbolAddress((void**)&p_woH,   g_woH);   cudaGetSymbolAddress((void**)&p_woL, g_woL);
    cudaGetSymbolAddress((void**)&p_w1H,   g_w1H);   cudaGetSymbolAddress((void**)&p_w1L, g_w1L);
    cudaGetSymbolAddress((void**)&p_w2H,   g_w2H);   cudaGetSymbolAddress((void**)&p_w2L, g_w2L);

    cudaFuncSetAttribute(gemm_bfp_k<0>, cudaFuncAttributeMaxDynamicSharedMemorySize, SMEM_DYN_BYTES);
    cudaFuncSetAttribute(gemm_bfp_k<1>, cudaFuncAttributeMaxDynamicSharedMemorySize, SMEM_DYN_BYTES);
    cudaFuncSetAttribute(gemm_bfp_k<2>, cudaFuncAttributeMaxDynamicSharedMemorySize, SMEM_DYN_BYTES);

    // 0. split weights to bf16 hi/lo planes
    wsplit_k<<<(DM * 2 * DI / 4 + 255) / 256, 256>>>(in_proj_w,  p_wiH, p_wiL, DM * 2 * DI / 4);
    wsplit_k<<<(DI * XDBL_W / 4 + 255) / 256, 256>>>(x_proj_w,   p_wxH, p_wxL, DI * XDBL_W / 4);
    wsplit_k<<<(DTRANK * DI / 4 + 255) / 256, 256>>>(dt_proj_w,  p_wdH, p_wdL, DTRANK * DI / 4);
    wsplit_k<<<(DI * DM / 4 + 255) / 256, 256>>>(out_proj_w, p_woH, p_woL, DI * DM / 4);
    wsplit_k<<<(DM * HID / 4 + 255) / 256, 256>>>(mlp_w1,     p_w1H, p_w1L, DM * HID / 4);
    wsplit_k<<<(HID * HID / 4 + 255) / 256, 256>>>(mlp_w2,     p_w2H, p_w2L, HID * HID / 4);

    // 1. layernorm -> bf16 hi/lo
    layernorm_bf_k<<<L_SEQ, 256>>>(vst, p_lnH, p_lnL, ln_w, ln_b, DM);

    // 2. in_proj: [4096,1024] @ [1024,4096]
    gemm_bfp_k<0><<<dim3(32, 32, 1), 512, SMEM_DYN_BYTES>>>(
        p_lnH, p_lnL, DM, p_wiH, p_wiL, 2*DI, p_xz, 2*DI, nullptr, nullptr, nullptr, 0,
        L_SEQ, 2*DI, DM);

    // 3. depthwise conv + silu -> fp32 + bf16
    conv_silu_k<<<(L_SEQ * DI) / 256, 256>>>(p_xz, conv_w, conv_b, p_u, p_uH, p_uL);

    // 4. x_proj: [4096,2048] @ [2048,96], split-K=8; reduce -> fp32 + bf16
    gemm_bfp_k<0><<<dim3(1, 32, 8), 512, SMEM_DYN_BYTES>>>(
        p_uH, p_uL, DI, p_wxH, p_wxL, XDBL_W, nullptr, 0, p_part, nullptr, nullptr, 0,
        L_SEQ, XDBL_W, DI);
    reduceK_k<0, 1, 1><<<(L_SEQ * XDBL_W / 4 + 255) / 256, 256>>>(
        p_part, 8, L_SEQ * XDBL_W, XDBL_W, nullptr, p_xdbl, p_xdH, p_xdL);

    // 5. dt_proj + softplus: [4096,64] @ [64,2048]
    gemm_bfp_k<1><<<dim3(16, 32, 1), 512, SMEM_DYN_BYTES>>>(
        p_xdH, p_xdL, XDBL_W, p_wdH, p_wdL, DI, p_dt, DI, nullptr, dt_proj_b, nullptr, 0,
        L_SEQ, DI, DTRANK);

    // 6. selective scan (3-pass chunked; scan1 restructured to thread-per-(chunk,d))
    a2_k<<<(DI * DSTATE) / 256, 256>>>(A_log, p_A2);
    scan1_k<<<(NCHUNK * DI) / 256, 256>>>(p_dt, p_u, p_xdbl, p_A2, p_Ap, p_Be);
    scan2_k<<<(DI * DSTATE) / 256, 256>>>(p_Ap, p_Be, p_hin);
    scan3_k<<<(NCHUNK * DI) / 256, 256>>>(p_dt, p_u, p_xdbl, p_A2, p_hin, D_param, p_xz, p_yH, p_yL);

    // 7. out_proj + residual: [4096,2048] @ [2048,1024] + vst
    gemm_bfp_k<2><<<dim3(8, 32, 1), 512, SMEM_DYN_BYTES>>>(
        p_yH, p_yL, DI, p_woH, p_woL, DM, p_mamba, DM, nullptr, nullptr, vst, DM,
        L_SEQ, DM, DI);

    // 8. final layernorm (fp32, feeds pool)
    layernorm_k<<<L_SEQ, 256>>>(p_mamba, p_ln2, fln_w, fln_b, DM);

    // 9. avg pool 4x4 -> bf16 hi/lo
    pool_k<<<(POOLED * DM) / 256, 256>>>(p_ln2, p_poolH, p_poolL);

    // 10. mlp1: [256,1024] @ [1024,4096], split-K=4; reduce gelu+bias -> bf16
    gemm_bfp_k<0><<<dim3(32, 2, 4), 512, SMEM_DYN_BYTES>>>(
        p_poolH, p_poolL, DM, p_w1H, p_w1L, HID, nullptr, 0, p_part, nullptr, nullptr, 0,
        POOLED, HID, DM);
    reduceK_k<3, 0, 1><<<(POOLED * HID / 4 + 255) / 256, 256>>>(
        p_part, 4, POOLED * HID, HID, mlp_b1, nullptr, p_midH, p_midL);

    // 11. mlp2: [256,4096] @ [4096,4096], split-K=8; reduce bias -> out fp32
    gemm_bfp_k<0><<<dim3(32, 2, 8), 512, SMEM_DYN_BYTES>>>(
        p_midH, p_midL, HID, p_w2H, p_w2L, HID, nullptr, 0, p_part, nullptr, nullptr, 0,
        POOLED, HID, HID);
    reduceK_k<4, 1, 0><<<(POOLED * HID / 4 + 255) / 256, 256>>>(
        p_part, 8, POOLED * HID, HID, mlp_b2, out, nullptr, nullptr);
}

// round 17
// speedup vs baseline: 1.4265x; 1.4265x over previous
#include <cuda_runtime.h>
#include <cuda_bf16.h>
#include <cstdint>

// ---------------- problem constants ----------------
#define L_SEQ   4096      // F*P = 16*256
#define DM      1024
#define DI      2048
#define DSTATE  16
#define DTRANK  64
#define XDBL_W  96        // DTRANK + 2*DSTATE
#define HID     4096
#define NCHUNK  16
#define CHUNKL  256       // L_SEQ / NCHUNK
#define POOLED  256       // 16 * 4 * 4

// smem geometry: A fp32 [128][40], B bf16 hi/lo planes [128][40] each; 2 stages
#define A_PAD     40
#define A_STG     (128 * A_PAD)            // 5120 floats  = 20480 B
#define BP_STG    (128 * A_PAD)            // 5120 bf16    = 10240 B per plane
#define STG_BYTES (A_STG * 4 + 2 * BP_STG * 2)   // 40960 B
#define SMEM_DYN_BYTES (2 * STG_BYTES)           // 81920 B

typedef __nv_bfloat16 bf16;

// ---------------- scratch (device globals; no cudaMalloc allowed) ----------------
__device__ float g_ln   [L_SEQ * DM];
__device__ float g_xz   [L_SEQ * 2 * DI];
__device__ float g_u    [L_SEQ * DI];
__device__ float g_xdbl [L_SEQ * XDBL_W];
__device__ float g_dt   [L_SEQ * DI];
__device__ float g_y    [L_SEQ * DI];
__device__ float g_mamba[L_SEQ * DM];
__device__ float g_ln2  [L_SEQ * DM];
__device__ float g_pool [POOLED * DM];
__device__ float g_mid  [POOLED * HID];
__device__ float g_A2   [DI * DSTATE];
__device__ float g_Ap   [NCHUNK * DI * DSTATE];
__device__ float g_Be   [NCHUNK * DI * DSTATE];
__device__ float g_hin  [NCHUNK * DI * DSTATE];
__device__ float g_part [8 * POOLED * HID];    // split-K partials

// transposed weight bf16 hi/lo planes, layout [N][K]
__device__ __align__(16) bf16 g_wiH [2 * DI * DM],   g_wiL [2 * DI * DM];
__device__ __align__(16) bf16 g_wxH [XDBL_W * DI],   g_wxL [XDBL_W * DI];
__device__ __align__(16) bf16 g_wdH [DI * DTRANK],   g_wdL [DI * DTRANK];
__device__ __align__(16) bf16 g_woH [DM * DI],       g_woL [DM * DI];
__device__ __align__(16) bf16 g_w1H [HID * DM],      g_w1L [HID * DM];
__device__ __align__(16) bf16 g_w2H [HID * HID],     g_w2L [HID * HID];

// ---------------- helpers ----------------
__device__ __forceinline__ float siluf(float x) { return x / (1.f + __expf(-x)); }
__device__ __forceinline__ float softplusf(float x) { return (x > 20.f) ? x : log1pf(__expf(x)); }
__device__ __forceinline__ float gelu_exact(float x) {
    return 0.5f * x * (1.f + erff(x * 0.70710678118654752440f));
}
__device__ __forceinline__ void split1(float v, bf16& h, bf16& l) {
    h = __float2bfloat16_rn(v);
    l = __float2bfloat16_rn(v - __bfloat162float(h));
}

__device__ __forceinline__ void cp_async16(const void* dst_smem, const void* src_gmem, bool pred) {
    uint32_t d = (uint32_t)__cvta_generic_to_shared(dst_smem);
    int sz = pred ? 16 : 0;
    asm volatile("cp.async.cg.shared.global [%0], [%1], 16, %2;\n"
                 :: "r"(d), "l"(src_gmem), "r"(sz));
}
__device__ __forceinline__ void cp_commit() { asm volatile("cp.async.commit_group;\n"); }
template<int N>
__device__ __forceinline__ void cp_wait() { asm volatile("cp.async.wait_group %0;\n" :: "n"(N)); }

// split fp32 pair (v0 = even-k, v1 = odd-k) into packed bf16x2 hi and lo parts
__device__ __forceinline__ void bf16split(float v0, float v1, uint32_t& hi, uint32_t& lo) {
    uint32_t h;
    asm("cvt.rn.bf16x2.f32 %0, %1, %2;" : "=r"(h) : "f"(v1), "f"(v0));
    float h0 = __uint_as_float(h << 16);
    float h1 = __uint_as_float(h & 0xFFFF0000u);
    float l0 = v0 - h0;
    float l1 = v1 - h1;
    uint32_t l;
    asm("cvt.rn.bf16x2.f32 %0, %1, %2;" : "=r"(l) : "f"(l1), "f"(l0));
    hi = h; lo = l;
}

__device__ __forceinline__ void mma_bf16(float* c, const uint32_t* a, const uint32_t* b) {
    asm volatile(
        "mma.sync.aligned.m16n8k16.row.col.f32.bf16.bf16.f32 "
        "{%0,%1,%2,%3}, {%4,%5,%6,%7}, {%8,%9}, {%0,%1,%2,%3};\n"
        : "+f"(c[0]), "+f"(c[1]), "+f"(c[2]), "+f"(c[3])
        : "r"(a[0]), "r"(a[1]), "r"(a[2]), "r"(a[3]), "r"(b[0]), "r"(b[1]));
}

// ---------------- weight split+transpose: W[K][N] fp32 -> H,L[N][K] bf16 ----------------
// 256-thread blocks (32x8), each handling a 32x32 tile.
__global__ void wsplitT_k(const float* __restrict__ W, bf16* __restrict__ H,
                          bf16* __restrict__ L, int K, int N) {
    __shared__ float t[32][33];
    int kb = blockIdx.y * 32, nb = blockIdx.x * 32;
    #pragma unroll
    for (int yy = threadIdx.y; yy < 32; yy += 8)
        t[yy][threadIdx.x] = W[(size_t)(kb + yy) * N + nb + threadIdx.x];
    __syncthreads();
    #pragma unroll
    for (int yy = threadIdx.y; yy < 32; yy += 8) {
        float v = t[threadIdx.x][yy];          // = W[kb+tx][nb+yy]
        bf16 h, l; split1(v, h, l);
        size_t o = (size_t)(nb + yy) * K + kb + threadIdx.x;
        H[o] = h; L[o] = l;
    }
}

// ---------------- layernorm: one block per row ----------------
__global__ void layernorm_k(const float* __restrict__ x, float* __restrict__ o,
                            const float* __restrict__ w, const float* __restrict__ b,
                            int cols) {
    int row = blockIdx.x;
    const float* xr = x + (size_t)row * cols;
    float s = 0.f, s2 = 0.f;
    for (int c = threadIdx.x; c < cols; c += blockDim.x) {
        float v = xr[c];
        s += v; s2 += v * v;
    }
    __shared__ float shs[8], shs2[8], shmu, shinv;
    for (int off = 16; off; off >>= 1) {
        s  += __shfl_down_sync(0xffffffffu, s,  off);
        s2 += __shfl_down_sync(0xffffffffu, s2, off);
    }
    int wid = threadIdx.x >> 5, lid = threadIdx.x & 31;
    if (!lid) { shs[wid] = s; shs2[wid] = s2; }
    __syncthreads();
    if (threadIdx.x == 0) {
        float ts = 0.f, ts2 = 0.f;
        int nw = blockDim.x >> 5;
        for (int i = 0; i < nw; ++i) { ts += shs[i]; ts2 += shs2[i]; }
        float mu = ts / cols;
        shmu = mu;
        shinv = rsqrtf(ts2 / cols - mu * mu + 1e-5f);
    }
    __syncthreads();
    float mu = shmu, inv = shinv;
    float* orow = o + (size_t)row * cols;
    for (int c = threadIdx.x; c < cols; c += blockDim.x)
        orow[c] = (xr[c] - mu) * inv * w[c] + b[c];
}

// ---------------- bf16x3 GEMM: A fp32 (inline split) x pre-split transposed B planes ----
// C[M,N] = epi(A@B); A [M][K] fp32 row-major; BT planes [N][K] bf16.
// C = Ah*Bh + Ah*Bl + Al*Bh (same arithmetic as round-8 kernel).
// Block 128x128x32, 512 thr = 16 warps (4x4), warp tile 32x32, 2-stage cp.async.
// EPI: 0 none, 1 bias+softplus, 2 +residual, 3 bias+gelu, 4 bias
template<int EPI>
__device__ __forceinline__ float epi_apply(float v, int r, int c,
                                           const float* bias,
                                           const float* res, int ldres) {
    if (EPI == 1) return softplusf(v + bias[c]);
    if (EPI == 2) return v + res[(size_t)r * ldres + c];
    if (EPI == 3) return gelu_exact(v + bias[c]);
    if (EPI == 4) return v + bias[c];
    return v;
}

template<int EPI>
__global__ __launch_bounds__(512, 1)
void gemm_bf16x3_k(const float* __restrict__ A, int lda,
                   const bf16* __restrict__ BTh, const bf16* __restrict__ BTl, int ldbt,
                   float* __restrict__ C, int ldc,
                   float* __restrict__ Cpart,
                   const float* __restrict__ bias,
                   const float* __restrict__ res, int ldres,
                   int M, int N, int K) {
    extern __shared__ char smc[];
    const int tid  = threadIdx.x;
    const int warp = tid >> 5;
    const int lane = tid & 31;
    const int grp  = lane >> 2;     // 0..7
    const int tig  = lane & 3;      // 0..3
    const int wm   = warp >> 2;     // 0..3
    const int wn   = warp & 3;      // 0..3
    const int row0 = blockIdx.y * 128;
    const int col0 = blockIdx.x * 128;
    const int kLen = K / gridDim.z;
    const int kBeg = blockIdx.z * kLen;
    const int nK   = kLen / 32;

    // loader coords: A 128 rows x 8 segs of 4 floats; B planes 128 rows x 4 segs of 8 bf16
    const int a_m0 = tid >> 3,  a_kq = tid & 7;
    const int a_m1 = (512 + tid) >> 3;
    const int b_n  = tid >> 2,  b_s  = tid & 3;
    const bool bp  = (col0 + b_n) < N;

    float acc[2][4][4];
    #pragma unroll
    for (int i = 0; i < 2; ++i)
        #pragma unroll
        for (int j = 0; j < 4; ++j)
            #pragma unroll
            for (int q = 0; q < 4; ++q) acc[i][j][q] = 0.f;

    auto issue_tile = [&](int stage, int k0) {
        float* AsS = (float*)(smc + stage * STG_BYTES);
        bf16*  BhS = (bf16*)(smc + stage * STG_BYTES + A_STG * 4);
        bf16*  BlS = BhS + BP_STG;
        cp_async16(AsS + a_m0 * A_PAD + a_kq * 4,
                   A + (size_t)(row0 + a_m0) * lda + k0 + a_kq * 4, true);
        cp_async16(AsS + a_m1 * A_PAD + a_kq * 4,
                   A + (size_t)(row0 + a_m1) * lda + k0 + a_kq * 4, true);
        cp_async16(BhS + b_n * A_PAD + b_s * 8,
                   BTh + (size_t)(col0 + b_n) * ldbt + k0 + b_s * 8, bp);
        cp_async16(BlS + b_n * A_PAD + b_s * 8,
                   BTl + (size_t)(col0 + b_n) * ldbt + k0 + b_s * 8, bp);
        cp_commit();
    };

    issue_tile(0, kBeg);

    for (int kt = 0; kt < nK; ++kt) {
        if (kt + 1 < nK) {
            issue_tile((kt + 1) & 1, kBeg + (kt + 1) * 32);
            cp_wait<1>();
        } else {
            cp_wait<0>();
        }
        __syncthreads();

        const float* AsS = (const float*)(smc + (kt & 1) * STG_BYTES);
        const bf16*  BhS = (const bf16*)(smc + (kt & 1) * STG_BYTES + A_STG * 4);
        const bf16*  BlS = BhS + BP_STG;

        #pragma unroll
        for (int ks = 0; ks < 32; ks += 16) {
            uint32_t ahi[2][4], alo[2][4], bhi[4][2], blo[4][2];
            #pragma unroll
            for (int i = 0; i < 2; ++i) {
                int m = wm * 32 + i * 16;
                float2 p0 = *reinterpret_cast<const float2*>(AsS + (m + grp    ) * A_PAD + ks + 2 * tig);
                float2 p1 = *reinterpret_cast<const float2*>(AsS + (m + grp + 8) * A_PAD + ks + 2 * tig);
                float2 p2 = *reinterpret_cast<const float2*>(AsS + (m + grp    ) * A_PAD + ks + 2 * tig + 8);
                float2 p3 = *reinterpret_cast<const float2*>(AsS + (m + grp + 8) * A_PAD + ks + 2 * tig + 8);
                bf16split(p0.x, p0.y, ahi[i][0], alo[i][0]);
                bf16split(p1.x, p1.y, ahi[i][1], alo[i][1]);
                bf16split(p2.x, p2.y, ahi[i][2], alo[i][2]);
                bf16split(p3.x, p3.y, ahi[i][3], alo[i][3]);
            }
            #pragma unroll
            for (int j = 0; j < 4; ++j) {
                int nb = (wn * 32 + j * 8 + grp) * A_PAD + ks + 2 * tig;
                bhi[j][0] = *reinterpret_cast<const uint32_t*>(BhS + nb);
                bhi[j][1] = *reinterpret_cast<const uint32_t*>(BhS + nb + 8);
                blo[j][0] = *reinterpret_cast<const uint32_t*>(BlS + nb);
                blo[j][1] = *reinterpret_cast<const uint32_t*>(BlS + nb + 8);
            }
            #pragma unroll
            for (int i = 0; i < 2; ++i)
                #pragma unroll
                for (int j = 0; j < 4; ++j) {
                    mma_bf16(acc[i][j], ahi[i], bhi[j]);
                    mma_bf16(acc[i][j], ahi[i], blo[j]);
                    mma_bf16(acc[i][j], alo[i], bhi[j]);
                }
        }
        __syncthreads();
    }

    // -------- write out --------
    if (gridDim.z > 1) {
        float* P = Cpart + (size_t)blockIdx.z * M * N;
        #pragma unroll
        for (int i = 0; i < 2; ++i)
            #pragma unroll
            for (int j = 0; j < 4; ++j) {
                int r = row0 + wm * 32 + i * 16 + grp;
                int c = col0 + wn * 32 + j * 8 + tig * 2;
                if (c < N) {
                    P[(size_t)r * N + c]       = acc[i][j][0];
                    P[(size_t)(r + 8) * N + c] = acc[i][j][2];
                }
                if (c + 1 < N) {
                    P[(size_t)r * N + c + 1]       = acc[i][j][1];
                    P[(size_t)(r + 8) * N + c + 1] = acc[i][j][3];
                }
            }
    } else {
        #pragma unroll
        for (int i = 0; i < 2; ++i)
            #pragma unroll
            for (int j = 0; j < 4; ++j) {
                int r = row0 + wm * 32 + i * 16 + grp;
                int c = col0 + wn * 32 + j * 8 + tig * 2;
                if (c < N) {
                    C[(size_t)r * ldc + c]       = epi_apply<EPI>(acc[i][j][0], r,     c,     bias, res, ldres);
                    C[(size_t)(r + 8) * ldc + c] = epi_apply<EPI>(acc[i][j][2], r + 8, c,     bias, res, ldres);
                }
                if (c + 1 < N) {
                    C[(size_t)r * ldc + c + 1]       = epi_apply<EPI>(acc[i][j][1], r,     c + 1, bias, res, ldres);
                    C[(size_t)(r + 8) * ldc + c + 1] = epi_apply<EPI>(acc[i][j][3], r + 8, c + 1, bias, res, ldres);
                }
            }
    }
}

// ---------------- split-K reduction with epilogue (float4) ----------------
template<int EPI>
__global__ void reduceK_k(const float* __restrict__ part, int S, int MN, int N,
                          const float* __restrict__ bias, float* __restrict__ out) {
    int idx4 = blockIdx.x * blockDim.x + threadIdx.x;
    if (idx4 * 4 >= MN) return;
    float4 s = make_float4(0.f, 0.f, 0.f, 0.f);
    for (int z = 0; z < S; ++z) {
        float4 v = *reinterpret_cast<const float4*>(part + (size_t)z * MN + idx4 * 4);
        s.x += v.x; s.y += v.y; s.z += v.z; s.w += v.w;
    }
    int c = (idx4 * 4) % N;
    if (EPI == 3) {
        s.x = gelu_exact(s.x + bias[c]);
        s.y = gelu_exact(s.y + bias[c + 1]);
        s.z = gelu_exact(s.z + bias[c + 2]);
        s.w = gelu_exact(s.w + bias[c + 3]);
    } else if (EPI == 4) {
        s.x += bias[c]; s.y += bias[c + 1]; s.z += bias[c + 2]; s.w += bias[c + 3];
    }
    *reinterpret_cast<float4*>(out + (size_t)idx4 * 4) = s;
}

// ---------------- depthwise causal conv (k=4) + silu ----------------
__global__ void conv_silu_k(const float* __restrict__ xz, const float* __restrict__ w,
                            const float* __restrict__ b, float* __restrict__ u) {
    int t = blockIdx.x * blockDim.x + threadIdx.x;
    if (t >= L_SEQ * DI) return;
    int l = t >> 11;
    int c = t & (DI - 1);
    float acc = b[c];
    #pragma unroll
    for (int k = 0; k < 4; ++k) {
        int ls = l - 3 + k;
        if (ls >= 0) acc = fmaf(w[c * 4 + k], xz[(size_t)ls * (2 * DI) + c], acc);
    }
    u[t] = siluf(acc);
}

// ---------------- A2 = -exp(A_log) * log2(e) ----------------
__global__ void a2_k(const float* __restrict__ A_log, float* __restrict__ A2) {
    int t = blockIdx.x * blockDim.x + threadIdx.x;
    if (t < DI * DSTATE) A2[t] = -__expf(A_log[t]) * 1.44269504088896f;
}

// ---------------- scan pass 1: per-chunk summaries, thread per (chunk,d) ----------------
__global__ void scan1_k(const float* __restrict__ dt, const float* __restrict__ u,
                        const float* __restrict__ xdbl, const float* __restrict__ A2,
                        float* __restrict__ Ap, float* __restrict__ Be) {
    int t = blockIdx.x * blockDim.x + threadIdx.x;
    if (t >= NCHUNK * DI) return;
    int chunk = t >> 11;
    int d = t & (DI - 1);
    float h[DSTATE], ap[DSTATE], a2[DSTATE];
    #pragma unroll
    for (int n = 0; n < DSTATE; ++n) {
        h[n] = 0.f; ap[n] = 1.f; a2[n] = A2[d * DSTATE + n];
    }
    int l0 = chunk * CHUNKL;
    for (int s = 0; s < CHUNKL; ++s) {
        int l = l0 + s;
        float dtv = dt[(size_t)l * DI + d];
        float uv  = u [(size_t)l * DI + d];
        float du  = dtv * uv;
        #pragma unroll
        for (int n = 0; n < DSTATE; ++n) {
            float a = exp2f(dtv * a2[n]);
            ap[n] *= a;
            h[n] = fmaf(a, h[n], du * xdbl[l * XDBL_W + DTRANK + n]);
        }
    }
    #pragma unroll
    for (int n = 0; n < DSTATE; ++n) {
        int idx = (chunk << 15) | (n << 11) | d;
        Ap[idx] = ap[n];
        Be[idx] = h[n];
    }
}

// ---------------- scan pass 2: inter-chunk sequential scan ----------------
__global__ void scan2_k(const float* __restrict__ Ap, const float* __restrict__ Be,
                        float* __restrict__ hin) {
    int t = blockIdx.x * blockDim.x + threadIdx.x;
    if (t >= DI * DSTATE) return;
    float h = 0.f;
    #pragma unroll
    for (int c = 0; c < NCHUNK; ++c) {
        hin[c * (DI * DSTATE) + t] = h;
        h = fmaf(Ap[c * (DI * DSTATE) + t], h, Be[c * (DI * DSTATE) + t]);
    }
}

// ---------------- scan pass 3: recompute + y, D-skip, silu gate ----------------
__global__ void scan3_k(const float* __restrict__ dt, const float* __restrict__ u,
                        const float* __restrict__ xdbl, const float* __restrict__ A2,
                        const float* __restrict__ hin, const float* __restrict__ Dp,
                        const float* __restrict__ xz, float* __restrict__ y) {
    int t = blockIdx.x * blockDim.x + threadIdx.x;
    if (t >= NCHUNK * DI) return;
    int chunk = t >> 11;
    int d = t & (DI - 1);
    float h[DSTATE], a2[DSTATE];
    #pragma unroll
    for (int n = 0; n < DSTATE; ++n) {
        h[n]  = hin[chunk * (DI * DSTATE) + n * DI + d];
        a2[n] = A2[d * DSTATE + n];
    }
    float Dd = Dp[d];
    int l0 = chunk * CHUNKL;
    for (int s = 0; s < CHUNKL; ++s) {
        int l = l0 + s;
        float dtv = dt[(size_t)l * DI + d];
        float uv  = u [(size_t)l * DI + d];
        float du  = dtv * uv;
        float acc = 0.f;
        #pragma unroll
        for (int n = 0; n < DSTATE; ++n) {
            float a = exp2f(dtv * a2[n]);
            h[n] = fmaf(a, h[n], du * xdbl[l * XDBL_W + DTRANK + n]);
            acc  = fmaf(h[n], xdbl[l * XDBL_W + DTRANK + DSTATE + n], acc);
        }
        acc = fmaf(uv, Dd, acc);
        float zv = xz[(size_t)l * (2 * DI) + DI + d];
        y[(size_t)l * DI + d] = acc * siluf(zv);
    }
}

// ---------------- avg pool 4x4 over (h,w) ----------------
__global__ void pool_k(const float* __restrict__ x, float* __restrict__ o) {
    int t = blockIdx.x * blockDim.x + threadIdx.x;
    if (t >= POOLED * DM) return;
    int d = t & (DM - 1);
    int po = t >> 10;
    int f = po >> 4, hh = (po >> 2) & 3, ww = po & 3;
    float s = 0.f;
    #pragma unroll
    for (int i = 0; i < 4; ++i)
        #pragma unroll
        for (int j = 0; j < 4; ++j) {
            int l = f * 256 + (hh * 4 + i) * 16 + (ww * 4 + j);
            s += x[(size_t)l * DM + d];
        }
    o[t] = s * 0.0625f;
}

// ---------------- launch ----------------
extern "C" void kernel_launch(void* const* d_in, const int* in_sizes, int n_in,
                              void* d_out, int out_size) {
    const float* vst        = (const float*)d_in[0];
    const float* ln_w       = (const float*)d_in[1];
    const float* ln_b       = (const float*)d_in[2];
    const float* in_proj_w  = (const float*)d_in[3];
    const float* conv_w     = (const float*)d_in[4];
    const float* conv_b     = (const float*)d_in[5];
    const float* x_proj_w   = (const float*)d_in[6];
    const float* dt_proj_w  = (const float*)d_in[7];
    const float* dt_proj_b  = (const float*)d_in[8];
    const float* A_log      = (const float*)d_in[9];
    const float* D_param    = (const float*)d_in[10];
    const float* out_proj_w = (const float*)d_in[11];
    const float* fln_w      = (const float*)d_in[12];
    const float* fln_b      = (const float*)d_in[13];
    const float* mlp_w1     = (const float*)d_in[14];
    const float* mlp_b1     = (const float*)d_in[15];
    const float* mlp_w2     = (const float*)d_in[16];
    const float* mlp_b2     = (const float*)d_in[17];
    float* out = (float*)d_out;

    float *p_ln, *p_xz, *p_u, *p_xdbl, *p_dt, *p_y, *p_mamba, *p_ln2,
          *p_pool, *p_mid, *p_A2, *p_Ap, *p_Be, *p_hin, *p_part;
    bf16 *p_wiH, *p_wiL, *p_wxH, *p_wxL, *p_wdH, *p_wdL, *p_woH, *p_woL,
         *p_w1H, *p_w1L, *p_w2H, *p_w2L;
    cudaGetSymbolAddress((void**)&p_ln,    g_ln);
    cudaGetSymbolAddress((void**)&p_xz,    g_xz);
    cudaGetSymbolAddress((void**)&p_u,     g_u);
    cudaGetSymbolAddress((void**)&p_xdbl,  g_xdbl);
    cudaGetSymbolAddress((void**)&p_dt,    g_dt);
    cudaGetSymbolAddress((void**)&p_y,     g_y);
    cudaGetSymbolAddress((void**)&p_mamba, g_mamba);
    cudaGetSymbolAddress((void**)&p_ln2,   g_ln2);
    cudaGetSymbolAddress((void**)&p_pool,  g_pool);
    cudaGetSymbolAddress((void**)&p_mid,   g_mid);
    cudaGetSymbolAddress((void**)&p_A2,    g_A2);
    cudaGetSymbolAddress((void**)&p_Ap,    g_Ap);
    cudaGetSymbolAddress((void**)&p_Be,    g_Be);
    cudaGetSymbolAddress((void**)&p_hin,   g_hin);
    cudaGetSymbolAddress((void**)&p_part,  g_part);
    cudaGetSymbolAddress((void**)&p_wiH,   g_wiH);   cudaGetSymbolAddress((void**)&p_wiL, g_wiL);
    cudaGetSymbolAddress((void**)&p_wxH,   g_wxH);   cudaGetSymbolAddress((void**)&p_wxL, g_wxL);
    cudaGetSymbolAddress((void**)&p_wdH,   g_wdH);   cudaGetSymbolAddress((void**)&p_wdL, g_wdL);
    cudaGetSymbolAddress((void**)&p_woH,   g_woH);   cudaGetSymbolAddress((void**)&p_woL, g_woL);
    cudaGetSymbolAddress((void**)&p_w1H,   g_w1H);   cudaGetSymbolAddress((void**)&p_w1L, g_w1L);
    cudaGetSymbolAddress((void**)&p_w2H,   g_w2H);   cudaGetSymbolAddress((void**)&p_w2L, g_w2L);

    cudaFuncSetAttribute(gemm_bf16x3_k<0>, cudaFuncAttributeMaxDynamicSharedMemorySize, SMEM_DYN_BYTES);
    cudaFuncSetAttribute(gemm_bf16x3_k<1>, cudaFuncAttributeMaxDynamicSharedMemorySize, SMEM_DYN_BYTES);
    cudaFuncSetAttribute(gemm_bf16x3_k<2>, cudaFuncAttributeMaxDynamicSharedMemorySize, SMEM_DYN_BYTES);

    // 0. split+transpose weights to bf16 hi/lo planes [N][K]  (256-thread blocks)
    {
        dim3 blk(32, 8);
        wsplitT_k<<<dim3((2*DI)/32, DM/32),    blk>>>(in_proj_w,  p_wiH, p_wiL, DM,     2*DI);
        wsplitT_k<<<dim3(XDBL_W/32, DI/32),    blk>>>(x_proj_w,   p_wxH, p_wxL, DI,     XDBL_W);
        wsplitT_k<<<dim3(DI/32, DTRANK/32),    blk>>>(dt_proj_w,  p_wdH, p_wdL, DTRANK, DI);
        wsplitT_k<<<dim3(DM/32, DI/32),        blk>>>(out_proj_w, p_woH, p_woL, DI,     DM);
        wsplitT_k<<<dim3(HID/32, DM/32),       blk>>>(mlp_w1,     p_w1H, p_w1L, DM,     HID);
        wsplitT_k<<<dim3(HID/32, HID/32),      blk>>>(mlp_w2,     p_w2H, p_w2L, HID,    HID);
    }

    // 1. layernorm
    layernorm_k<<<L_SEQ, 256>>>(vst, p_ln, ln_w, ln_b, DM);

    // 2. in_proj: [4096,1024] @ [1024,4096]
    gemm_bf16x3_k<0><<<dim3(32, 32, 1), 512, SMEM_DYN_BYTES>>>(
        p_ln, DM, p_wiH, p_wiL, DM, p_xz, 2*DI, nullptr, nullptr, nullptr, 0,
        L_SEQ, 2*DI, DM);

    // 3. depthwise conv + silu
    conv_silu_k<<<(L_SEQ * DI) / 256, 256>>>(p_xz, conv_w, conv_b, p_u);

    // 4. x_proj: [4096,2048] @ [2048,96], split-K=8
    gemm_bf16x3_k<0><<<dim3(1, 32, 8), 512, SMEM_DYN_BYTES>>>(
        p_u, DI, p_wxH, p_wxL, DI, nullptr, 0, p_part, nullptr, nullptr, 0,
        L_SEQ, XDBL_W, DI);
    reduceK_k<0><<<(L_SEQ * XDBL_W / 4 + 255) / 256, 256>>>(
        p_part, 8, L_SEQ * XDBL_W, XDBL_W, nullptr, p_xdbl);

    // 5. dt_proj + softplus: [4096,64] @ [64,2048]
    gemm_bf16x3_k<1><<<dim3(16, 32, 1), 512, SMEM_DYN_BYTES>>>(
        p_xdbl, XDBL_W, p_wdH, p_wdL, DTRANK, p_dt, DI, nullptr, dt_proj_b, nullptr, 0,
        L_SEQ, DI, DTRANK);

    // 6. selective scan (3-pass chunked)
    a2_k<<<(DI * DSTATE) / 256, 256>>>(A_log, p_A2);
    scan1_k<<<(NCHUNK * DI) / 256, 256>>>(p_dt, p_u, p_xdbl, p_A2, p_Ap, p_Be);
    scan2_k<<<(DI * DSTATE) / 256, 256>>>(p_Ap, p_Be, p_hin);
    scan3_k<<<(NCHUNK * DI) / 256, 256>>>(p_dt, p_u, p_xdbl, p_A2, p_hin, D_param, p_xz, p_y);

    // 7. out_proj + residual: [4096,2048] @ [2048,1024] + vst
    gemm_bf16x3_k<2><<<dim3(8, 32, 1), 512, SMEM_DYN_BYTES>>>(
        p_y, DI, p_woH, p_woL, DI, p_mamba, DM, nullptr, nullptr, vst, DM,
        L_SEQ, DM, DI);

    // 8. final layernorm
    layernorm_k<<<L_SEQ, 256>>>(p_mamba, p_ln2, fln_w, fln_b, DM);

    // 9. avg pool 4x4
    pool_k<<<(POOLED * DM) / 256, 256>>>(p_ln2, p_pool);

    // 10. mlp1: [256,1024] @ [1024,4096], split-K=4, gelu+bias epilogue in reduce
    gemm_bf16x3_k<0><<<dim3(32, 2, 4), 512, SMEM_DYN_BYTES>>>(
        p_pool, DM, p_w1H, p_w1L, DM, nullptr, 0, p_part, nullptr, nullptr, 0,
        POOLED, HID, DM);
    reduceK_k<3><<<(POOLED * HID / 4 + 255) / 256, 256>>>(
        p_part, 4, POOLED * HID, HID, mlp_b1, p_mid);

    // 11. mlp2: [256,4096] @ [4096,4096], split-K=8, bias epilogue in reduce
    gemm_bf16x3_k<0><<<dim3(32, 2, 8), 512, SMEM_DYN_BYTES>>>(
        p_mid, HID, p_w2H, p_w2L, HID, nullptr, 0, p_part, nullptr, nullptr, 0,
        POOLED, HID, HID);
    reduceK_k<4><<<(POOLED * HID / 4 + 255) / 256, 256>>>(
        p_part, 8, POOLED * HID, HID, mlp_b2, out);
}